// round 12
// baseline (speedup 1.0000x reference)
#include <cuda_runtime.h>
#include <cuda_fp16.h>
#include <cstdint>

#define N_ROWS  16384
#define D_DIM   512
#define K_CODES 8192

#define BM 128
#define BN 128
#define KC 128           // depth per chunk
#define NKC 4            // 512/128
#define NTILE 64         // 8192/128
#define STAGES 3
#define PITCH_B 272      // 256 data bytes + 16 pad (conflict-free ldmatrix)
#define PLANE_BYTES (128 * PITCH_B)          // 34816
#define STAGE_BYTES (2 * PLANE_BYTES)        // 69632 (A plane + B plane)
#define SMEM_DYN (STAGES * STAGE_BYTES)      // 208896

// ---------------- device scratch (static: no allocations) ----------------
__device__ __half g_xh[N_ROWS * D_DIM];
__device__ __half g_wh[K_CODES * D_DIM];
__device__ float g_wnorm[K_CODES];
__device__ int4  g_cand[N_ROWS];
__device__ float g_loss;

// ---------------- helpers ----------------
__device__ __forceinline__ uint32_t smem_u32(const void* p) {
    uint32_t a;
    asm("{ .reg .u64 t; cvta.to.shared.u64 t, %1; cvt.u32.u64 %0, t; }" : "=r"(a) : "l"(p));
    return a;
}

__device__ __forceinline__ void ldsm4(uint32_t* r, uint32_t addr) {
    asm volatile("ldmatrix.sync.aligned.m8n8.x4.shared.b16 {%0,%1,%2,%3}, [%4];"
                 : "=r"(r[0]), "=r"(r[1]), "=r"(r[2]), "=r"(r[3]) : "r"(addr));
}

__device__ __forceinline__ void mma16816(float* c, const uint32_t* a,
                                         uint32_t b0, uint32_t b1) {
    asm volatile(
        "mma.sync.aligned.m16n8k16.row.col.f32.f16.f16.f32 "
        "{%0,%1,%2,%3}, {%4,%5,%6,%7}, {%8,%9}, {%0,%1,%2,%3};"
        : "+f"(c[0]), "+f"(c[1]), "+f"(c[2]), "+f"(c[3])
        : "r"(a[0]), "r"(a[1]), "r"(a[2]), "r"(a[3]), "r"(b0), "r"(b1));
}

#define CP_ASYNC16(dst, src) \
    asm volatile("cp.async.cg.shared.global [%0], [%1], 16;" :: "r"(dst), "l"(src))
#define CP_COMMIT()   asm volatile("cp.async.commit_group;" ::: "memory")
#define CP_WAIT(n)    asm volatile("cp.async.wait_group %0;" :: "n"(n) : "memory")

// ============================================================
// convert X -> fp16
// ============================================================
__global__ void split_x_kernel(const float* __restrict__ src) {
    int i = blockIdx.x * blockDim.x + threadIdx.x;   // over float4s
    float4 v = reinterpret_cast<const float4*>(src)[i];
    reinterpret_cast<__half2*>(g_xh)[i * 2]     = __floats2half2_rn(v.x, v.y);
    reinterpret_cast<__half2*>(g_xh)[i * 2 + 1] = __floats2half2_rn(v.z, v.w);
}

// ============================================================
// convert W -> fp16, compute ||w||^2, zero loss  (one pass over W)
// ============================================================
__global__ void split_wnorm_kernel(const float* __restrict__ W) {
    int k = blockIdx.x;
    const float* row = W + (size_t)k * D_DIM;
    int d = threadIdx.x * 4;
    float4 v = *reinterpret_cast<const float4*>(row + d);
    __half2* dst = reinterpret_cast<__half2*>(g_wh + (size_t)k * D_DIM + d);
    dst[0] = __floats2half2_rn(v.x, v.y);
    dst[1] = __floats2half2_rn(v.z, v.w);
    float s = v.x * v.x + v.y * v.y + v.z * v.z + v.w * v.w;
    #pragma unroll
    for (int o = 16; o > 0; o >>= 1) s += __shfl_xor_sync(0xffffffffu, s, o);
    __shared__ float sm[4];
    if ((threadIdx.x & 31) == 0) sm[threadIdx.x >> 5] = s;
    __syncthreads();
    if (threadIdx.x == 0) {
        g_wnorm[k] = sm[0] + sm[1] + sm[2] + sm[3];
        if (k == 0) g_loss = 0.f;
    }
}

// ============================================================
// fused fp16 HMMA GEMM + top-4 argmax candidates
// grid = 128 row tiles, 512 threads (16 warps, 4x4), warp tile 32x32
// ============================================================
__global__ void __launch_bounds__(512, 1)
argmin_mma() {
    extern __shared__ __align__(16) char smem[];
    const uint32_t sb = smem_u32(smem);
    const int tid  = threadIdx.x;
    const int lane = tid & 31;
    const int wid  = tid >> 5;
    const int wm = wid >> 2;          // 0..3 : 32-row slab
    const int wn = wid & 3;           // 0..3 : 32-col slab
    const int row0 = blockIdx.x * BM;

    const uint32_t lm_off = (uint32_t)((lane & 15) * PITCH_B + (lane >> 4) * 16);
    const uint32_t a_base_row = (uint32_t)(wm * 32) * PITCH_B;
    const uint32_t b_base_row = (uint32_t)(wn * 32) * PITCH_B;

    float acc[2][4][4];
    #pragma unroll
    for (int am = 0; am < 2; ++am)
        #pragma unroll
        for (int an = 0; an < 4; ++an)
            #pragma unroll
            for (int j = 0; j < 4; ++j) acc[am][an][j] = 0.f;

    // per-thread top-2 per (am, h) row
    float b1[2][2], b2[2][2];
    int   i1[2][2], i2[2][2];
    #pragma unroll
    for (int am = 0; am < 2; ++am)
        #pragma unroll
        for (int h = 0; h < 2; ++h) {
            b1[am][h] = b2[am][h] = -3.4e38f;
            i1[am][h] = i2[am][h] = 0;
        }

    float wnv[4][2];

    // 2 planes per stage: 0 = A (this CTA's X rows), 1 = W.
    auto load_chunk = [&](int g) {
        const int st = g % STAGES, cg = g & (NKC - 1), tg = g >> 2;
        const uint32_t dbase = sb + (uint32_t)st * STAGE_BYTES;
        #pragma unroll
        for (int it = 0; it < 8; ++it) {
            int v = it * 512 + tid;
            int p = v >> 11;          // plane (0..1)
            int rem = v & 2047;
            int r = rem >> 4, j = rem & 15;
            const __half* s0 =
                (p == 0 ? g_xh + (size_t)(row0 + r) * D_DIM
                        : g_wh + (size_t)(tg * BN + r) * D_DIM)
                + cg * KC + j * 8;
            uint32_t dst = dbase + (uint32_t)(p * PLANE_BYTES + r * PITCH_B + j * 16);
            CP_ASYNC16(dst, s0);
        }
    };

    auto load_wn = [&](int t) {
        #pragma unroll
        for (int an = 0; an < 4; ++an)
            #pragma unroll
            for (int p = 0; p < 2; ++p)
                wnv[an][p] = 0.5f * __ldg(&g_wnorm[t * BN + wn * 32 + an * 8 + (lane & 3) * 2 + p]);
    };

    // prologue
    load_chunk(0); CP_COMMIT();
    load_chunk(1); CP_COMMIT();
    load_wn(0);

    int tile = 0;
    const int TOTAL = NTILE * NKC;   // 256
    for (int g = 0; g < TOTAL; ++g) {
        // issue next-next chunk FIRST, then wait with depth 2:
        // after this commit, total committed = g+3 groups; chunk g ready
        // iff pending <= 2.
        if (g + 2 < TOTAL) load_chunk(g + 2);
        CP_COMMIT();
        CP_WAIT(2);
        __syncthreads();

        const uint32_t base = sb + (uint32_t)(g % STAGES) * STAGE_BYTES;
        #pragma unroll
        for (int ks = 0; ks < 8; ++ks) {
            uint32_t ah[2][4], bh[2][4];
            #pragma unroll
            for (int am = 0; am < 2; ++am) {
                uint32_t ad = base + a_base_row + (uint32_t)(am * 16 * PITCH_B) + lm_off + ks * 32;
                ldsm4(ah[am], ad);
            }
            #pragma unroll
            for (int bp = 0; bp < 2; ++bp) {
                uint32_t bd = base + PLANE_BYTES + b_base_row + (uint32_t)(bp * 16 * PITCH_B) + lm_off + ks * 32;
                ldsm4(bh[bp], bd);
            }
            #pragma unroll
            for (int am = 0; am < 2; ++am)
                #pragma unroll
                for (int an = 0; an < 4; ++an)
                    mma16816(acc[am][an], ah[am], bh[an >> 1][an & 1], bh[an >> 1][(an & 1) + 2]);
        }

        if ((g & (NKC - 1)) == (NKC - 1)) {
            // epilogue: score = dot - 0.5*||w||^2, running top-2
            #pragma unroll
            for (int am = 0; am < 2; ++am)
                #pragma unroll
                for (int an = 0; an < 4; ++an)
                    #pragma unroll
                    for (int j = 0; j < 4; ++j) {
                        int h = j >> 1, p = j & 1;
                        float m = acc[am][an][j] - wnv[an][p];
                        int col = tile * BN + wn * 32 + an * 8 + (lane & 3) * 2 + p;
                        if (m > b1[am][h]) {
                            b2[am][h] = b1[am][h]; i2[am][h] = i1[am][h];
                            b1[am][h] = m;         i1[am][h] = col;
                        } else if (m > b2[am][h]) {
                            b2[am][h] = m;         i2[am][h] = col;
                        }
                        acc[am][an][j] = 0.f;
                    }
            ++tile;
            if (tile < NTILE) load_wn(tile);
        }
    }

    CP_WAIT(0);
    __syncthreads();

    // cross-thread reduction to global top-4: 16 slots x 2 candidates per row
    float* rb1 = reinterpret_cast<float*>(smem);
    float* rb2 = rb1 + BM * 16;
    int*   ri1 = reinterpret_cast<int*>(rb2 + BM * 16);
    int*   ri2 = ri1 + BM * 16;
    #pragma unroll
    for (int am = 0; am < 2; ++am)
        #pragma unroll
        for (int h = 0; h < 2; ++h) {
            int rl = wm * 32 + am * 16 + h * 8 + (lane >> 2);
            int slot = wn * 4 + (lane & 3);
            rb1[rl * 16 + slot] = b1[am][h];
            rb2[rl * 16 + slot] = b2[am][h];
            ri1[rl * 16 + slot] = i1[am][h];
            ri2[rl * 16 + slot] = i2[am][h];
        }
    __syncthreads();
    if (tid < BM) {
        float B[4] = {-3.4e38f, -3.4e38f, -3.4e38f, -3.4e38f};
        int   I[4] = {0, 0, 0, 0};
        #pragma unroll
        for (int s = 0; s < 16; ++s) {
            #pragma unroll
            for (int q = 0; q < 2; ++q) {
                float v = q ? rb2[tid * 16 + s] : rb1[tid * 16 + s];
                int   ii = q ? ri2[tid * 16 + s] : ri1[tid * 16 + s];
                #pragma unroll
                for (int r = 0; r < 4; ++r) {
                    if (v > B[r] || (v == B[r] && ii < I[r])) {
                        #pragma unroll
                        for (int q2 = 3; q2 > r; --q2) { B[q2] = B[q2 - 1]; I[q2] = I[q2 - 1]; }
                        B[r] = v; I[r] = ii;
                        break;
                    }
                }
            }
        }
        g_cand[row0 + tid] = make_int4(I[0], I[1], I[2], I[3]);
    }
}

// ============================================================
// fused fixup + gather + loss: one block (128 thr) per row.
// Warp w rescores candidate w in fp64 (4 independent accumulators),
// then warp 0 selects, then all threads gather + loss.
// ============================================================
__global__ void __launch_bounds__(128)
fixup_gather_kernel(const float* __restrict__ X,
                    const float* __restrict__ W,
                    float* __restrict__ out) {
    const int row  = blockIdx.x;
    const int tid  = threadIdx.x;
    const int wid  = tid >> 5;
    const int lane = tid & 31;
    const int4 cd = g_cand[row];
    const int cand[4] = {cd.x, cd.y, cd.z, cd.w};
    const int myk = cand[wid];
    const float* xr = X + (size_t)row * D_DIM;

    __shared__ double ssc[4];
    __shared__ int sbk;

    // d(k) = sum_d w*(w - 2x)   (||x||^2 dropped); 4 independent chains
    {
        const float* wr = W + (size_t)myk * D_DIM;
        double s0 = 0.0, s1 = 0.0, s2 = 0.0, s3 = 0.0;
        #pragma unroll
        for (int j = 0; j < 4; ++j) {
            int dd = lane * 4 + j * 128;
            float4 w4 = *reinterpret_cast<const float4*>(wr + dd);
            float4 x4 = *reinterpret_cast<const float4*>(xr + dd);
            s0 += (double)w4.x * ((double)w4.x - 2.0 * (double)x4.x);
            s1 += (double)w4.y * ((double)w4.y - 2.0 * (double)x4.y);
            s2 += (double)w4.z * ((double)w4.z - 2.0 * (double)x4.z);
            s3 += (double)w4.w * ((double)w4.w - 2.0 * (double)x4.w);
        }
        double s = (s0 + s1) + (s2 + s3);
        #pragma unroll
        for (int o = 16; o > 0; o >>= 1)
            s += __shfl_xor_sync(0xffffffffu, s, o);
        if (lane == 0) ssc[wid] = s;
    }
    __syncthreads();
    if (tid == 0) {
        double bd = ssc[0];
        int bk = cand[0];
        #pragma unroll
        for (int c = 1; c < 4; ++c) {
            double s = ssc[c];
            int k = cand[c];
            if (s < bd || (s == bd && k < bk)) { bd = s; bk = k; }
        }
        sbk = bk;
    }
    __syncthreads();
    const int bk = sbk;

    // gather + loss: 128 threads x float4 = 512 elements
    const float* wr = W + (size_t)bk * D_DIM;
    float* orow = out + (size_t)row * D_DIM;
    int d = tid * 4;
    float4 q  = *reinterpret_cast<const float4*>(wr + d);
    float4 xv = *reinterpret_cast<const float4*>(xr + d);
    *reinterpret_cast<float4*>(orow + d) = q;
    float dx = q.x - xv.x, dy = q.y - xv.y, dz = q.z - xv.z, dw = q.w - xv.w;
    float s = dx * dx + dy * dy + dz * dz + dw * dw;
    #pragma unroll
    for (int o = 16; o > 0; o >>= 1) s += __shfl_xor_sync(0xffffffffu, s, o);
    __shared__ float sm[4];
    if (lane == 0) sm[wid] = s;
    __syncthreads();
    if (tid == 0) atomicAdd(&g_loss, sm[0] + sm[1] + sm[2] + sm[3]);
}

__global__ void loss_kernel(float* __restrict__ out, int pos) {
    out[pos] = 1.25f * g_loss / (float)(N_ROWS * D_DIM);
}

// ============================================================
extern "C" void kernel_launch(void* const* d_in, const int* in_sizes, int n_in,
                              void* d_out, int out_size) {
    const float* x = (const float*)d_in[0];
    const float* W = (const float*)d_in[1];
    if (in_sizes[0] == K_CODES * D_DIM && in_sizes[1] == N_ROWS * D_DIM) {
        const float* t = x; x = W; W = t;
    }
    float* out = (float*)d_out;

    cudaFuncSetAttribute(argmin_mma, cudaFuncAttributeMaxDynamicSharedMemorySize, SMEM_DYN);

    split_x_kernel     <<<(N_ROWS * D_DIM / 4) / 256, 256>>>(x);
    split_wnorm_kernel <<<K_CODES, 128>>>(W);
    argmin_mma         <<<N_ROWS / BM, 512, SMEM_DYN>>>();
    fixup_gather_kernel<<<N_ROWS, 128>>>(x, W, out);
    loss_kernel        <<<1, 1>>>(out, out_size - 1);
}

// round 13
// speedup vs baseline: 1.7249x; 1.7249x over previous
#include <cuda_runtime.h>
#include <cuda_fp16.h>
#include <cstdint>

#define N_ROWS  16384
#define D_DIM   512
#define K_CODES 8192

#define BM 128
#define BN 128
#define KC 128           // depth per chunk
#define NKC 4            // 512/128
#define NTILE 64         // 8192/128
#define STAGES 3
#define PITCH_B 272      // 256 data bytes + 16 pad (conflict-free ldmatrix)
#define PLANE_BYTES (128 * PITCH_B)          // 34816
#define STAGE_BYTES (2 * PLANE_BYTES)        // 69632 (A plane + B plane)
#define SMEM_DYN (STAGES * STAGE_BYTES)      // 208896

#define NFIX (N_ROWS / 8)                    // 2048 fixup blocks

// ---------------- device scratch (static: no allocations) ----------------
__device__ __half g_xh[N_ROWS * D_DIM];
__device__ __half g_wh[K_CODES * D_DIM];
__device__ float g_wnorm[K_CODES];
__device__ int4  g_cand[N_ROWS];
__device__ float g_partial[NFIX];

// ---------------- helpers ----------------
__device__ __forceinline__ uint32_t smem_u32(const void* p) {
    uint32_t a;
    asm("{ .reg .u64 t; cvta.to.shared.u64 t, %1; cvt.u32.u64 %0, t; }" : "=r"(a) : "l"(p));
    return a;
}

__device__ __forceinline__ void ldsm4(uint32_t* r, uint32_t addr) {
    asm volatile("ldmatrix.sync.aligned.m8n8.x4.shared.b16 {%0,%1,%2,%3}, [%4];"
                 : "=r"(r[0]), "=r"(r[1]), "=r"(r[2]), "=r"(r[3]) : "r"(addr));
}

__device__ __forceinline__ void mma16816(float* c, const uint32_t* a,
                                         uint32_t b0, uint32_t b1) {
    asm volatile(
        "mma.sync.aligned.m16n8k16.row.col.f32.f16.f16.f32 "
        "{%0,%1,%2,%3}, {%4,%5,%6,%7}, {%8,%9}, {%0,%1,%2,%3};"
        : "+f"(c[0]), "+f"(c[1]), "+f"(c[2]), "+f"(c[3])
        : "r"(a[0]), "r"(a[1]), "r"(a[2]), "r"(a[3]), "r"(b0), "r"(b1));
}

#define CP_ASYNC16(dst, src) \
    asm volatile("cp.async.cg.shared.global [%0], [%1], 16;" :: "r"(dst), "l"(src))
#define CP_COMMIT()   asm volatile("cp.async.commit_group;" ::: "memory")
#define CP_WAIT(n)    asm volatile("cp.async.wait_group %0;" :: "n"(n) : "memory")

// ============================================================
// convert X -> fp16
// ============================================================
__global__ void split_x_kernel(const float* __restrict__ src) {
    int i = blockIdx.x * blockDim.x + threadIdx.x;   // over float4s
    float4 v = reinterpret_cast<const float4*>(src)[i];
    reinterpret_cast<__half2*>(g_xh)[i * 2]     = __floats2half2_rn(v.x, v.y);
    reinterpret_cast<__half2*>(g_xh)[i * 2 + 1] = __floats2half2_rn(v.z, v.w);
}

// ============================================================
// convert W -> fp16 + ||w||^2  (one pass over W)
// ============================================================
__global__ void split_wnorm_kernel(const float* __restrict__ W) {
    int k = blockIdx.x;
    const float* row = W + (size_t)k * D_DIM;
    int d = threadIdx.x * 4;
    float4 v = *reinterpret_cast<const float4*>(row + d);
    __half2* dst = reinterpret_cast<__half2*>(g_wh + (size_t)k * D_DIM + d);
    dst[0] = __floats2half2_rn(v.x, v.y);
    dst[1] = __floats2half2_rn(v.z, v.w);
    float s = v.x * v.x + v.y * v.y + v.z * v.z + v.w * v.w;
    #pragma unroll
    for (int o = 16; o > 0; o >>= 1) s += __shfl_xor_sync(0xffffffffu, s, o);
    __shared__ float sm[4];
    if ((threadIdx.x & 31) == 0) sm[threadIdx.x >> 5] = s;
    __syncthreads();
    if (threadIdx.x == 0) g_wnorm[k] = sm[0] + sm[1] + sm[2] + sm[3];
}

// ============================================================
// fused fp16 HMMA GEMM + top-4 argmax candidates
// grid = 128 row tiles, 512 threads (16 warps, 4x4), warp tile 32x32
// ============================================================
__global__ void __launch_bounds__(512, 1)
argmin_mma() {
    extern __shared__ __align__(16) char smem[];
    const uint32_t sb = smem_u32(smem);
    const int tid  = threadIdx.x;
    const int lane = tid & 31;
    const int wid  = tid >> 5;
    const int wm = wid >> 2;          // 0..3 : 32-row slab
    const int wn = wid & 3;           // 0..3 : 32-col slab
    const int row0 = blockIdx.x * BM;

    const uint32_t lm_off = (uint32_t)((lane & 15) * PITCH_B + (lane >> 4) * 16);
    const uint32_t a_base_row = (uint32_t)(wm * 32) * PITCH_B;
    const uint32_t b_base_row = (uint32_t)(wn * 32) * PITCH_B;

    float acc[2][4][4];
    #pragma unroll
    for (int am = 0; am < 2; ++am)
        #pragma unroll
        for (int an = 0; an < 4; ++an)
            #pragma unroll
            for (int j = 0; j < 4; ++j) acc[am][an][j] = 0.f;

    // per-thread top-2 per (am, h) row
    float b1[2][2], b2[2][2];
    int   i1[2][2], i2[2][2];
    #pragma unroll
    for (int am = 0; am < 2; ++am)
        #pragma unroll
        for (int h = 0; h < 2; ++h) {
            b1[am][h] = b2[am][h] = -3.4e38f;
            i1[am][h] = i2[am][h] = 0;
        }

    float wnv[4][2];

    // 2 planes per stage: 0 = A (this CTA's X rows), 1 = W.
    auto load_chunk = [&](int g) {
        const int st = g % STAGES, cg = g & (NKC - 1), tg = g >> 2;
        const uint32_t dbase = sb + (uint32_t)st * STAGE_BYTES;
        #pragma unroll
        for (int it = 0; it < 8; ++it) {
            int v = it * 512 + tid;
            int p = v >> 11;          // plane (0..1)
            int rem = v & 2047;
            int r = rem >> 4, j = rem & 15;
            const __half* s0 =
                (p == 0 ? g_xh + (size_t)(row0 + r) * D_DIM
                        : g_wh + (size_t)(tg * BN + r) * D_DIM)
                + cg * KC + j * 8;
            uint32_t dst = dbase + (uint32_t)(p * PLANE_BYTES + r * PITCH_B + j * 16);
            CP_ASYNC16(dst, s0);
        }
    };

    auto load_wn = [&](int t) {
        #pragma unroll
        for (int an = 0; an < 4; ++an)
            #pragma unroll
            for (int p = 0; p < 2; ++p)
                wnv[an][p] = 0.5f * __ldg(&g_wnorm[t * BN + wn * 32 + an * 8 + (lane & 3) * 2 + p]);
    };

    // prologue
    load_chunk(0); CP_COMMIT();
    load_chunk(1); CP_COMMIT();
    load_wn(0);

    int tile = 0;
    const int TOTAL = NTILE * NKC;   // 256
    for (int g = 0; g < TOTAL; ++g) {
        CP_WAIT(1);
        __syncthreads();
        if (g + 2 < TOTAL) load_chunk(g + 2);
        CP_COMMIT();

        const uint32_t base = sb + (uint32_t)(g % STAGES) * STAGE_BYTES;
        #pragma unroll
        for (int ks = 0; ks < 8; ++ks) {
            uint32_t ah[2][4], bh[2][4];
            #pragma unroll
            for (int am = 0; am < 2; ++am) {
                uint32_t ad = base + a_base_row + (uint32_t)(am * 16 * PITCH_B) + lm_off + ks * 32;
                ldsm4(ah[am], ad);
            }
            #pragma unroll
            for (int bp = 0; bp < 2; ++bp) {
                uint32_t bd = base + PLANE_BYTES + b_base_row + (uint32_t)(bp * 16 * PITCH_B) + lm_off + ks * 32;
                ldsm4(bh[bp], bd);
            }
            #pragma unroll
            for (int am = 0; am < 2; ++am)
                #pragma unroll
                for (int an = 0; an < 4; ++an)
                    mma16816(acc[am][an], ah[am], bh[an >> 1][an & 1], bh[an >> 1][(an & 1) + 2]);
        }

        if ((g & (NKC - 1)) == (NKC - 1)) {
            // epilogue: score = dot - 0.5*||w||^2, running top-2
            #pragma unroll
            for (int am = 0; am < 2; ++am)
                #pragma unroll
                for (int an = 0; an < 4; ++an)
                    #pragma unroll
                    for (int j = 0; j < 4; ++j) {
                        int h = j >> 1, p = j & 1;
                        float m = acc[am][an][j] - wnv[an][p];
                        int col = tile * BN + wn * 32 + an * 8 + (lane & 3) * 2 + p;
                        if (m > b1[am][h]) {
                            b2[am][h] = b1[am][h]; i2[am][h] = i1[am][h];
                            b1[am][h] = m;         i1[am][h] = col;
                        } else if (m > b2[am][h]) {
                            b2[am][h] = m;         i2[am][h] = col;
                        }
                        acc[am][an][j] = 0.f;
                    }
            ++tile;
            if (tile < NTILE) load_wn(tile);
        }
    }

    CP_WAIT(0);
    __syncthreads();

    // cross-thread reduction to global top-4: 16 slots x 2 candidates per row
    float* rb1 = reinterpret_cast<float*>(smem);
    float* rb2 = rb1 + BM * 16;
    int*   ri1 = reinterpret_cast<int*>(rb2 + BM * 16);
    int*   ri2 = ri1 + BM * 16;
    #pragma unroll
    for (int am = 0; am < 2; ++am)
        #pragma unroll
        for (int h = 0; h < 2; ++h) {
            int rl = wm * 32 + am * 16 + h * 8 + (lane >> 2);
            int slot = wn * 4 + (lane & 3);
            rb1[rl * 16 + slot] = b1[am][h];
            rb2[rl * 16 + slot] = b2[am][h];
            ri1[rl * 16 + slot] = i1[am][h];
            ri2[rl * 16 + slot] = i2[am][h];
        }
    __syncthreads();
    if (tid < BM) {
        float B[4] = {-3.4e38f, -3.4e38f, -3.4e38f, -3.4e38f};
        int   I[4] = {0, 0, 0, 0};
        #pragma unroll
        for (int s = 0; s < 16; ++s) {
            #pragma unroll
            for (int q = 0; q < 2; ++q) {
                float v = q ? rb2[tid * 16 + s] : rb1[tid * 16 + s];
                int   ii = q ? ri2[tid * 16 + s] : ri1[tid * 16 + s];
                #pragma unroll
                for (int r = 0; r < 4; ++r) {
                    if (v > B[r] || (v == B[r] && ii < I[r])) {
                        #pragma unroll
                        for (int q2 = 3; q2 > r; --q2) { B[q2] = B[q2 - 1]; I[q2] = I[q2 - 1]; }
                        B[r] = v; I[r] = ii;
                        break;
                    }
                }
            }
        }
        g_cand[row0 + tid] = make_int4(I[0], I[1], I[2], I[3]);
    }
}

// ============================================================
// fused fixup + gather + loss (NO global atomics):
// warp per row (8 rows/block); fp64 rescore 4 candidates with
// 4 independent accumulators; per-block partial -> g_partial[bid]
// ============================================================
__global__ void __launch_bounds__(256)
fixup_gather_kernel(const float* __restrict__ X,
                    const float* __restrict__ W,
                    float* __restrict__ out) {
    const int tid  = threadIdx.x;
    const int wid  = tid >> 5;
    const int lane = tid & 31;
    const int row  = blockIdx.x * 8 + wid;
    const int4 cd = g_cand[row];
    const int cand[4] = {cd.x, cd.y, cd.z, cd.w};
    const float* xr = X + (size_t)row * D_DIM;

    double bd = 1e300;
    int bk = 0x7fffffff;
    #pragma unroll
    for (int c = 0; c < 4; ++c) {
        int k = cand[c];
        const float* wr = W + (size_t)k * D_DIM;
        double s0 = 0.0, s1 = 0.0, s2 = 0.0, s3 = 0.0;
        #pragma unroll
        for (int j = 0; j < 4; ++j) {
            int dd = lane * 4 + j * 128;
            float4 w4 = *reinterpret_cast<const float4*>(wr + dd);
            float4 x4 = *reinterpret_cast<const float4*>(xr + dd);
            s0 += (double)w4.x * ((double)w4.x - 2.0 * (double)x4.x);
            s1 += (double)w4.y * ((double)w4.y - 2.0 * (double)x4.y);
            s2 += (double)w4.z * ((double)w4.z - 2.0 * (double)x4.z);
            s3 += (double)w4.w * ((double)w4.w - 2.0 * (double)x4.w);
        }
        double s = (s0 + s1) + (s2 + s3);
        #pragma unroll
        for (int o = 16; o > 0; o >>= 1)
            s += __shfl_xor_sync(0xffffffffu, s, o);
        // all lanes hold identical s -> identical (bd, bk)
        if (s < bd || (s == bd && k < bk)) { bd = s; bk = k; }
    }

    // gather + per-warp loss
    const float* wr = W + (size_t)bk * D_DIM;
    float* orow = out + (size_t)row * D_DIM;
    float s = 0.f;
    #pragma unroll
    for (int j = 0; j < 4; ++j) {
        int dd = lane * 4 + j * 128;
        float4 q  = *reinterpret_cast<const float4*>(wr + dd);
        float4 xv = *reinterpret_cast<const float4*>(xr + dd);
        *reinterpret_cast<float4*>(orow + dd) = q;
        float dx = q.x - xv.x, dy = q.y - xv.y, dz = q.z - xv.z, dw = q.w - xv.w;
        s += dx * dx + dy * dy + dz * dz + dw * dw;
    }
    #pragma unroll
    for (int o = 16; o > 0; o >>= 1) s += __shfl_xor_sync(0xffffffffu, s, o);
    __shared__ float sm[8];
    if (lane == 0) sm[wid] = s;
    __syncthreads();
    if (tid == 0) {
        float t = 0.f;
        #pragma unroll
        for (int i = 0; i < 8; ++i) t += sm[i];
        g_partial[blockIdx.x] = t;   // distinct address per block -> no atomic
    }
}

// ============================================================
// final loss: reduce 2048 partials (1 block, 256 threads)
// ============================================================
__global__ void __launch_bounds__(256)
loss_kernel(float* __restrict__ out, int pos) {
    int tid = threadIdx.x;
    float s = 0.f;
    #pragma unroll
    for (int i = 0; i < NFIX / 256; ++i)
        s += g_partial[i * 256 + tid];
    #pragma unroll
    for (int o = 16; o > 0; o >>= 1) s += __shfl_xor_sync(0xffffffffu, s, o);
    __shared__ float sm[8];
    if ((tid & 31) == 0) sm[tid >> 5] = s;
    __syncthreads();
    if (tid == 0) {
        float t = 0.f;
        #pragma unroll
        for (int i = 0; i < 8; ++i) t += sm[i];
        out[pos] = 1.25f * t / (float)(N_ROWS * D_DIM);
    }
}

// ============================================================
extern "C" void kernel_launch(void* const* d_in, const int* in_sizes, int n_in,
                              void* d_out, int out_size) {
    const float* x = (const float*)d_in[0];
    const float* W = (const float*)d_in[1];
    if (in_sizes[0] == K_CODES * D_DIM && in_sizes[1] == N_ROWS * D_DIM) {
        const float* t = x; x = W; W = t;
    }
    float* out = (float*)d_out;

    cudaFuncSetAttribute(argmin_mma, cudaFuncAttributeMaxDynamicSharedMemorySize, SMEM_DYN);

    split_x_kernel     <<<(N_ROWS * D_DIM / 4) / 256, 256>>>(x);
    split_wnorm_kernel <<<K_CODES, 128>>>(W);
    argmin_mma         <<<N_ROWS / BM, 512, SMEM_DYN>>>();
    fixup_gather_kernel<<<NFIX, 256>>>(x, W, out);
    loss_kernel        <<<1, 256>>>(out, out_size - 1);
}

// round 14
// speedup vs baseline: 2.4236x; 1.4051x over previous
#include <cuda_runtime.h>
#include <cuda_fp16.h>
#include <cstdint>

#define N_ROWS  16384
#define D_DIM   512
#define K_CODES 8192

#define BM 128
#define BN 128
#define KC 128           // depth per chunk
#define NKC 4            // 512/128
#define NTILE 64         // 8192/128
#define STAGES 3
#define PITCH_B 272      // 256 data bytes + 16 pad (conflict-free ldmatrix)
#define PLANE_BYTES (128 * PITCH_B)          // 34816
#define STAGE_BYTES (2 * PLANE_BYTES)        // 69632 (A plane + B plane)
#define SMEM_DYN (STAGES * STAGE_BYTES)      // 208896

#define NFIX (N_ROWS / 8)                    // 2048 fixup blocks

// ---------------- device scratch (static: no allocations) ----------------
__device__ __half g_xh[N_ROWS * D_DIM];
__device__ __half g_wh[K_CODES * D_DIM];
__device__ float g_wnorm[K_CODES];
__device__ int4  g_cand[N_ROWS];
__device__ float g_partial[NFIX];

// ---------------- helpers ----------------
__device__ __forceinline__ uint32_t smem_u32(const void* p) {
    uint32_t a;
    asm("{ .reg .u64 t; cvta.to.shared.u64 t, %1; cvt.u32.u64 %0, t; }" : "=r"(a) : "l"(p));
    return a;
}

__device__ __forceinline__ void ldsm4(uint32_t* r, uint32_t addr) {
    asm volatile("ldmatrix.sync.aligned.m8n8.x4.shared.b16 {%0,%1,%2,%3}, [%4];"
                 : "=r"(r[0]), "=r"(r[1]), "=r"(r[2]), "=r"(r[3]) : "r"(addr));
}

__device__ __forceinline__ void mma16816(float* c, const uint32_t* a,
                                         uint32_t b0, uint32_t b1) {
    asm volatile(
        "mma.sync.aligned.m16n8k16.row.col.f32.f16.f16.f32 "
        "{%0,%1,%2,%3}, {%4,%5,%6,%7}, {%8,%9}, {%0,%1,%2,%3};"
        : "+f"(c[0]), "+f"(c[1]), "+f"(c[2]), "+f"(c[3])
        : "r"(a[0]), "r"(a[1]), "r"(a[2]), "r"(a[3]), "r"(b0), "r"(b1));
}

#define CP_ASYNC16(dst, src) \
    asm volatile("cp.async.cg.shared.global [%0], [%1], 16;" :: "r"(dst), "l"(src))
#define CP_COMMIT()   asm volatile("cp.async.commit_group;" ::: "memory")
#define CP_WAIT(n)    asm volatile("cp.async.wait_group %0;" :: "n"(n) : "memory")

// ============================================================
// convert X -> fp16
// ============================================================
__global__ void split_x_kernel(const float* __restrict__ src) {
    int i = blockIdx.x * blockDim.x + threadIdx.x;   // over float4s
    float4 v = reinterpret_cast<const float4*>(src)[i];
    reinterpret_cast<__half2*>(g_xh)[i * 2]     = __floats2half2_rn(v.x, v.y);
    reinterpret_cast<__half2*>(g_xh)[i * 2 + 1] = __floats2half2_rn(v.z, v.w);
}

// ============================================================
// convert W -> fp16 + ||w||^2  (one pass over W)
// ============================================================
__global__ void split_wnorm_kernel(const float* __restrict__ W) {
    int k = blockIdx.x;
    const float* row = W + (size_t)k * D_DIM;
    int d = threadIdx.x * 4;
    float4 v = *reinterpret_cast<const float4*>(row + d);
    __half2* dst = reinterpret_cast<__half2*>(g_wh + (size_t)k * D_DIM + d);
    dst[0] = __floats2half2_rn(v.x, v.y);
    dst[1] = __floats2half2_rn(v.z, v.w);
    float s = v.x * v.x + v.y * v.y + v.z * v.z + v.w * v.w;
    #pragma unroll
    for (int o = 16; o > 0; o >>= 1) s += __shfl_xor_sync(0xffffffffu, s, o);
    __shared__ float sm[4];
    if ((threadIdx.x & 31) == 0) sm[threadIdx.x >> 5] = s;
    __syncthreads();
    if (threadIdx.x == 0) g_wnorm[k] = sm[0] + sm[1] + sm[2] + sm[3];
}

// ============================================================
// fused fp16 HMMA GEMM + top-4 argmax candidates
// grid = 128 row tiles, 512 threads (16 warps, 4x4), warp tile 32x32
// ============================================================
__global__ void __launch_bounds__(512, 1)
argmin_mma() {
    extern __shared__ __align__(16) char smem[];
    const uint32_t sb = smem_u32(smem);
    const int tid  = threadIdx.x;
    const int lane = tid & 31;
    const int wid  = tid >> 5;
    const int wm = wid >> 2;          // 0..3 : 32-row slab
    const int wn = wid & 3;           // 0..3 : 32-col slab
    const int row0 = blockIdx.x * BM;

    const uint32_t lm_off = (uint32_t)((lane & 15) * PITCH_B + (lane >> 4) * 16);
    const uint32_t a_base_row = (uint32_t)(wm * 32) * PITCH_B;
    const uint32_t b_base_row = (uint32_t)(wn * 32) * PITCH_B;

    float acc[2][4][4];
    #pragma unroll
    for (int am = 0; am < 2; ++am)
        #pragma unroll
        for (int an = 0; an < 4; ++an)
            #pragma unroll
            for (int j = 0; j < 4; ++j) acc[am][an][j] = 0.f;

    // per-thread top-2 per (am, h) row
    float b1[2][2], b2[2][2];
    int   i1[2][2], i2[2][2];
    #pragma unroll
    for (int am = 0; am < 2; ++am)
        #pragma unroll
        for (int h = 0; h < 2; ++h) {
            b1[am][h] = b2[am][h] = -3.4e38f;
            i1[am][h] = i2[am][h] = 0;
        }

    float wnv[4][2];

    // 2 planes per stage: 0 = A (this CTA's X rows), 1 = W.
    auto load_chunk = [&](int g) {
        const int st = g % STAGES, cg = g & (NKC - 1), tg = g >> 2;
        const uint32_t dbase = sb + (uint32_t)st * STAGE_BYTES;
        #pragma unroll
        for (int it = 0; it < 8; ++it) {
            int v = it * 512 + tid;
            int p = v >> 11;          // plane (0..1)
            int rem = v & 2047;
            int r = rem >> 4, j = rem & 15;
            const __half* s0 =
                (p == 0 ? g_xh + (size_t)(row0 + r) * D_DIM
                        : g_wh + (size_t)(tg * BN + r) * D_DIM)
                + cg * KC + j * 8;
            uint32_t dst = dbase + (uint32_t)(p * PLANE_BYTES + r * PITCH_B + j * 16);
            CP_ASYNC16(dst, s0);
        }
    };

    auto load_wn = [&](int t) {
        #pragma unroll
        for (int an = 0; an < 4; ++an)
            #pragma unroll
            for (int p = 0; p < 2; ++p)
                wnv[an][p] = 0.5f * __ldg(&g_wnorm[t * BN + wn * 32 + an * 8 + (lane & 3) * 2 + p]);
    };

    // prologue
    load_chunk(0); CP_COMMIT();
    load_chunk(1); CP_COMMIT();
    load_wn(0);

    int tile = 0;
    const int TOTAL = NTILE * NKC;   // 256
    for (int g = 0; g < TOTAL; ++g) {
        CP_WAIT(1);
        __syncthreads();
        if (g + 2 < TOTAL) load_chunk(g + 2);
        CP_COMMIT();

        const uint32_t base = sb + (uint32_t)(g % STAGES) * STAGE_BYTES;
        #pragma unroll
        for (int ks = 0; ks < 8; ++ks) {
            uint32_t ah[2][4], bh[2][4];
            #pragma unroll
            for (int am = 0; am < 2; ++am) {
                uint32_t ad = base + a_base_row + (uint32_t)(am * 16 * PITCH_B) + lm_off + ks * 32;
                ldsm4(ah[am], ad);
            }
            #pragma unroll
            for (int bp = 0; bp < 2; ++bp) {
                uint32_t bd = base + PLANE_BYTES + b_base_row + (uint32_t)(bp * 16 * PITCH_B) + lm_off + ks * 32;
                ldsm4(bh[bp], bd);
            }
            #pragma unroll
            for (int am = 0; am < 2; ++am)
                #pragma unroll
                for (int an = 0; an < 4; ++an)
                    mma16816(acc[am][an], ah[am], bh[an >> 1][an & 1], bh[an >> 1][(an & 1) + 2]);
        }

        if ((g & (NKC - 1)) == (NKC - 1)) {
            // epilogue: score = dot - 0.5*||w||^2, running top-2
            #pragma unroll
            for (int am = 0; am < 2; ++am)
                #pragma unroll
                for (int an = 0; an < 4; ++an)
                    #pragma unroll
                    for (int j = 0; j < 4; ++j) {
                        int h = j >> 1, p = j & 1;
                        float m = acc[am][an][j] - wnv[an][p];
                        int col = tile * BN + wn * 32 + an * 8 + (lane & 3) * 2 + p;
                        if (m > b1[am][h]) {
                            b2[am][h] = b1[am][h]; i2[am][h] = i1[am][h];
                            b1[am][h] = m;         i1[am][h] = col;
                        } else if (m > b2[am][h]) {
                            b2[am][h] = m;         i2[am][h] = col;
                        }
                        acc[am][an][j] = 0.f;
                    }
            ++tile;
            if (tile < NTILE) load_wn(tile);
        }
    }

    CP_WAIT(0);
    __syncthreads();

    // cross-thread reduction to global top-4: 16 slots x 2 candidates per row
    float* rb1 = reinterpret_cast<float*>(smem);
    float* rb2 = rb1 + BM * 16;
    int*   ri1 = reinterpret_cast<int*>(rb2 + BM * 16);
    int*   ri2 = ri1 + BM * 16;
    #pragma unroll
    for (int am = 0; am < 2; ++am)
        #pragma unroll
        for (int h = 0; h < 2; ++h) {
            int rl = wm * 32 + am * 16 + h * 8 + (lane >> 2);
            int slot = wn * 4 + (lane & 3);
            rb1[rl * 16 + slot] = b1[am][h];
            rb2[rl * 16 + slot] = b2[am][h];
            ri1[rl * 16 + slot] = i1[am][h];
            ri2[rl * 16 + slot] = i2[am][h];
        }
    __syncthreads();
    if (tid < BM) {
        float B[4] = {-3.4e38f, -3.4e38f, -3.4e38f, -3.4e38f};
        int   I[4] = {0, 0, 0, 0};
        #pragma unroll
        for (int s = 0; s < 16; ++s) {
            #pragma unroll
            for (int q = 0; q < 2; ++q) {
                float v = q ? rb2[tid * 16 + s] : rb1[tid * 16 + s];
                int   ii = q ? ri2[tid * 16 + s] : ri1[tid * 16 + s];
                #pragma unroll
                for (int r = 0; r < 4; ++r) {
                    if (v > B[r] || (v == B[r] && ii < I[r])) {
                        #pragma unroll
                        for (int q2 = 3; q2 > r; --q2) { B[q2] = B[q2 - 1]; I[q2] = I[q2 - 1]; }
                        B[r] = v; I[r] = ii;
                        break;
                    }
                }
            }
        }
        g_cand[row0 + tid] = make_int4(I[0], I[1], I[2], I[3]);
    }
}

// ============================================================
// fused fixup + gather + loss (fp32 rescore — B300 fp64 is rate-limited):
// warp per row (8 rows/block); rescore 4 candidates with 4 independent
// fp32 FFMA accumulators + tree reduction; per-block partial loss.
// d(k) = sum_d w*(w - 2x)   (||x||^2 dropped, row-constant)
// ============================================================
__global__ void __launch_bounds__(256)
fixup_gather_kernel(const float* __restrict__ X,
                    const float* __restrict__ W,
                    float* __restrict__ out) {
    const int tid  = threadIdx.x;
    const int wid  = tid >> 5;
    const int lane = tid & 31;
    const int row  = blockIdx.x * 8 + wid;
    const int4 cd = g_cand[row];
    const int cand[4] = {cd.x, cd.y, cd.z, cd.w};
    const float* xr = X + (size_t)row * D_DIM;

    // cache this row's x in registers (reused across 4 candidates)
    float4 xv[4];
    #pragma unroll
    for (int j = 0; j < 4; ++j)
        xv[j] = *reinterpret_cast<const float4*>(xr + lane * 4 + j * 128);

    float bdist = 3.4e38f;
    int   bk = 0x7fffffff;
    #pragma unroll
    for (int c = 0; c < 4; ++c) {
        int k = cand[c];
        const float* wr = W + (size_t)k * D_DIM;
        float s0 = 0.f, s1 = 0.f, s2 = 0.f, s3 = 0.f;
        #pragma unroll
        for (int j = 0; j < 4; ++j) {
            float4 w4 = *reinterpret_cast<const float4*>(wr + lane * 4 + j * 128);
            s0 = fmaf(w4.x, fmaf(-2.f, xv[j].x, w4.x), s0);
            s1 = fmaf(w4.y, fmaf(-2.f, xv[j].y, w4.y), s1);
            s2 = fmaf(w4.z, fmaf(-2.f, xv[j].z, w4.z), s2);
            s3 = fmaf(w4.w, fmaf(-2.f, xv[j].w, w4.w), s3);
        }
        float s = (s0 + s1) + (s2 + s3);
        #pragma unroll
        for (int o = 16; o > 0; o >>= 1)
            s += __shfl_xor_sync(0xffffffffu, s, o);
        // all lanes hold identical s -> identical (bdist, bk)
        if (s < bdist || (s == bdist && k < bk)) { bdist = s; bk = k; }
    }

    // gather + per-warp loss
    const float* wr = W + (size_t)bk * D_DIM;
    float* orow = out + (size_t)row * D_DIM;
    float s = 0.f;
    #pragma unroll
    for (int j = 0; j < 4; ++j) {
        int dd = lane * 4 + j * 128;
        float4 q = *reinterpret_cast<const float4*>(wr + dd);
        *reinterpret_cast<float4*>(orow + dd) = q;
        float dx = q.x - xv[j].x, dy = q.y - xv[j].y, dz = q.z - xv[j].z, dw = q.w - xv[j].w;
        s += dx * dx + dy * dy + dz * dz + dw * dw;
    }
    #pragma unroll
    for (int o = 16; o > 0; o >>= 1) s += __shfl_xor_sync(0xffffffffu, s, o);
    __shared__ float sm[8];
    if (lane == 0) sm[wid] = s;
    __syncthreads();
    if (tid == 0) {
        float t = 0.f;
        #pragma unroll
        for (int i = 0; i < 8; ++i) t += sm[i];
        g_partial[blockIdx.x] = t;   // distinct address per block -> no atomic
    }
}

// ============================================================
// final loss: reduce 2048 partials (1 block, 256 threads)
// ============================================================
__global__ void __launch_bounds__(256)
loss_kernel(float* __restrict__ out, int pos) {
    int tid = threadIdx.x;
    float s = 0.f;
    #pragma unroll
    for (int i = 0; i < NFIX / 256; ++i)
        s += g_partial[i * 256 + tid];
    #pragma unroll
    for (int o = 16; o > 0; o >>= 1) s += __shfl_xor_sync(0xffffffffu, s, o);
    __shared__ float sm[8];
    if ((tid & 31) == 0) sm[tid >> 5] = s;
    __syncthreads();
    if (tid == 0) {
        float t = 0.f;
        #pragma unroll
        for (int i = 0; i < 8; ++i) t += sm[i];
        out[pos] = 1.25f * t / (float)(N_ROWS * D_DIM);
    }
}

// ============================================================
extern "C" void kernel_launch(void* const* d_in, const int* in_sizes, int n_in,
                              void* d_out, int out_size) {
    const float* x = (const float*)d_in[0];
    const float* W = (const float*)d_in[1];
    if (in_sizes[0] == K_CODES * D_DIM && in_sizes[1] == N_ROWS * D_DIM) {
        const float* t = x; x = W; W = t;
    }
    float* out = (float*)d_out;

    cudaFuncSetAttribute(argmin_mma, cudaFuncAttributeMaxDynamicSharedMemorySize, SMEM_DYN);

    split_x_kernel     <<<(N_ROWS * D_DIM / 4) / 256, 256>>>(x);
    split_wnorm_kernel <<<K_CODES, 128>>>(W);
    argmin_mma         <<<N_ROWS / BM, 512, SMEM_DYN>>>();
    fixup_gather_kernel<<<NFIX, 256>>>(x, W, out);
    loss_kernel        <<<1, 256>>>(out, out_size - 1);
}

// round 15
// speedup vs baseline: 2.7551x; 1.1368x over previous
#include <cuda_runtime.h>
#include <cuda_fp16.h>
#include <cstdint>

#define N_ROWS  16384
#define D_DIM   512
#define K_CODES 8192

#define BM 128
#define BN 128
#define KC 128           // depth per chunk
#define NKC 4            // 512/128
#define NTILE 64         // 8192/128
#define PITCH_B 272      // 256 data bytes + 16 pad (conflict-free ldmatrix)
#define PLANE_BYTES (128 * PITCH_B)          // 34816
#define A_BYTES (NKC * PLANE_BYTES)          // 139264 (A resident: 4 chunk planes)
#define SMEM_DYN (A_BYTES + 2 * PLANE_BYTES) // 208896 (A + 2 W stages)

#define NFIX (N_ROWS / 8)                    // 2048 fixup blocks

// ---------------- device scratch (static: no allocations) ----------------
__device__ __half g_xh[N_ROWS * D_DIM];
__device__ __half g_wh[K_CODES * D_DIM];
__device__ float g_wnorm[K_CODES];
__device__ int4  g_cand[N_ROWS];
__device__ float g_partial[NFIX];

// ---------------- helpers ----------------
__device__ __forceinline__ uint32_t smem_u32(const void* p) {
    uint32_t a;
    asm("{ .reg .u64 t; cvta.to.shared.u64 t, %1; cvt.u32.u64 %0, t; }" : "=r"(a) : "l"(p));
    return a;
}

__device__ __forceinline__ void ldsm4(uint32_t* r, uint32_t addr) {
    asm volatile("ldmatrix.sync.aligned.m8n8.x4.shared.b16 {%0,%1,%2,%3}, [%4];"
                 : "=r"(r[0]), "=r"(r[1]), "=r"(r[2]), "=r"(r[3]) : "r"(addr));
}

__device__ __forceinline__ void mma16816(float* c, const uint32_t* a,
                                         uint32_t b0, uint32_t b1) {
    asm volatile(
        "mma.sync.aligned.m16n8k16.row.col.f32.f16.f16.f32 "
        "{%0,%1,%2,%3}, {%4,%5,%6,%7}, {%8,%9}, {%0,%1,%2,%3};"
        : "+f"(c[0]), "+f"(c[1]), "+f"(c[2]), "+f"(c[3])
        : "r"(a[0]), "r"(a[1]), "r"(a[2]), "r"(a[3]), "r"(b0), "r"(b1));
}

#define CP_ASYNC16(dst, src) \
    asm volatile("cp.async.cg.shared.global [%0], [%1], 16;" :: "r"(dst), "l"(src))
#define CP_COMMIT()   asm volatile("cp.async.commit_group;" ::: "memory")
#define CP_WAIT(n)    asm volatile("cp.async.wait_group %0;" :: "n"(n) : "memory")

// ============================================================
// convert X -> fp16
// ============================================================
__global__ void split_x_kernel(const float* __restrict__ src) {
    int i = blockIdx.x * blockDim.x + threadIdx.x;   // over float4s
    float4 v = reinterpret_cast<const float4*>(src)[i];
    reinterpret_cast<__half2*>(g_xh)[i * 2]     = __floats2half2_rn(v.x, v.y);
    reinterpret_cast<__half2*>(g_xh)[i * 2 + 1] = __floats2half2_rn(v.z, v.w);
}

// ============================================================
// convert W -> fp16 + ||w||^2  (one pass over W)
// ============================================================
__global__ void split_wnorm_kernel(const float* __restrict__ W) {
    int k = blockIdx.x;
    const float* row = W + (size_t)k * D_DIM;
    int d = threadIdx.x * 4;
    float4 v = *reinterpret_cast<const float4*>(row + d);
    __half2* dst = reinterpret_cast<__half2*>(g_wh + (size_t)k * D_DIM + d);
    dst[0] = __floats2half2_rn(v.x, v.y);
    dst[1] = __floats2half2_rn(v.z, v.w);
    float s = v.x * v.x + v.y * v.y + v.z * v.z + v.w * v.w;
    #pragma unroll
    for (int o = 16; o > 0; o >>= 1) s += __shfl_xor_sync(0xffffffffu, s, o);
    __shared__ float sm[4];
    if ((threadIdx.x & 31) == 0) sm[threadIdx.x >> 5] = s;
    __syncthreads();
    if (threadIdx.x == 0) g_wnorm[k] = sm[0] + sm[1] + sm[2] + sm[3];
}

// ============================================================
// fused fp16 HMMA GEMM + top-4 argmax candidates
// A (X tile) RESIDENT in smem; W streamed, 2 stages, prefetch dist 1
// grid = 128 row tiles, 512 threads (16 warps, 4x4), warp tile 32x32
// ============================================================
__global__ void __launch_bounds__(512, 1)
argmin_mma() {
    extern __shared__ __align__(16) char smem[];
    const uint32_t sb = smem_u32(smem);
    const int tid  = threadIdx.x;
    const int lane = tid & 31;
    const int wid  = tid >> 5;
    const int wm = wid >> 2;          // 0..3 : 32-row slab
    const int wn = wid & 3;           // 0..3 : 32-col slab
    const int row0 = blockIdx.x * BM;

    const uint32_t lm_off = (uint32_t)((lane & 15) * PITCH_B + (lane >> 4) * 16);
    const uint32_t a_base_row = (uint32_t)(wm * 32) * PITCH_B;
    const uint32_t b_base_row = (uint32_t)(wn * 32) * PITCH_B;

    float acc[2][4][4];
    #pragma unroll
    for (int am = 0; am < 2; ++am)
        #pragma unroll
        for (int an = 0; an < 4; ++an)
            #pragma unroll
            for (int j = 0; j < 4; ++j) acc[am][an][j] = 0.f;

    // per-thread top-2 per (am, h) row
    float b1[2][2], b2[2][2];
    int   i1[2][2], i2[2][2];
    #pragma unroll
    for (int am = 0; am < 2; ++am)
        #pragma unroll
        for (int h = 0; h < 2; ++h) {
            b1[am][h] = b2[am][h] = -3.4e38f;
            i1[am][h] = i2[am][h] = 0;
        }

    float wnv[4][2];

    // A resident: 4 chunk-planes of 128 rows x 256B. 8192 cp16 / 512 thr = 16.
    auto load_A = [&]() {
        #pragma unroll
        for (int it = 0; it < 16; ++it) {
            int v = it * 512 + tid;
            int cg = v >> 11;          // chunk plane 0..3
            int rem = v & 2047;
            int r = rem >> 4, j = rem & 15;
            const __half* s0 = g_xh + (size_t)(row0 + r) * D_DIM + cg * KC + j * 8;
            uint32_t dst = sb + (uint32_t)(cg * PLANE_BYTES + r * PITCH_B + j * 16);
            CP_ASYNC16(dst, s0);
        }
    };

    // W chunk g: tile tg = g>>2, depth chunk cg = g&3 -> stage g&1.
    // 2048 cp16 / 512 thr = 4.
    auto load_W = [&](int g) {
        const int st = g & 1, cg = g & (NKC - 1), tg = g >> 2;
        const uint32_t dbase = sb + A_BYTES + (uint32_t)st * PLANE_BYTES;
        #pragma unroll
        for (int it = 0; it < 4; ++it) {
            int v = it * 512 + tid;
            int r = v >> 4, j = v & 15;
            const __half* s0 = g_wh + (size_t)(tg * BN + r) * D_DIM + cg * KC + j * 8;
            uint32_t dst = dbase + (uint32_t)(r * PITCH_B + j * 16);
            CP_ASYNC16(dst, s0);
        }
    };

    auto load_wn = [&](int t) {
        #pragma unroll
        for (int an = 0; an < 4; ++an)
            #pragma unroll
            for (int p = 0; p < 2; ++p)
                wnv[an][p] = 0.5f * __ldg(&g_wnorm[t * BN + wn * 32 + an * 8 + (lane & 3) * 2 + p]);
    };

    // prologue: A resident + W chunk 0
    load_A(); CP_COMMIT();
    load_W(0); CP_COMMIT();
    load_wn(0);

    int tile = 0;
    const int TOTAL = NTILE * NKC;   // 256
    for (int g = 0; g < TOTAL; ++g) {
        CP_WAIT(0);              // chunk g (and A) landed
        __syncthreads();         // all warps done with the stage being overwritten
        if (g + 1 < TOTAL) load_W(g + 1);
        CP_COMMIT();

        const uint32_t abase = sb + (uint32_t)(g & (NKC - 1)) * PLANE_BYTES;
        const uint32_t wbase = sb + A_BYTES + (uint32_t)(g & 1) * PLANE_BYTES;
        #pragma unroll
        for (int ks = 0; ks < 8; ++ks) {
            uint32_t ah[2][4], bh[2][4];
            #pragma unroll
            for (int am = 0; am < 2; ++am) {
                uint32_t ad = abase + a_base_row + (uint32_t)(am * 16 * PITCH_B) + lm_off + ks * 32;
                ldsm4(ah[am], ad);
            }
            #pragma unroll
            for (int bp = 0; bp < 2; ++bp) {
                uint32_t bd = wbase + b_base_row + (uint32_t)(bp * 16 * PITCH_B) + lm_off + ks * 32;
                ldsm4(bh[bp], bd);
            }
            #pragma unroll
            for (int am = 0; am < 2; ++am)
                #pragma unroll
                for (int an = 0; an < 4; ++an)
                    mma16816(acc[am][an], ah[am], bh[an >> 1][an & 1], bh[an >> 1][(an & 1) + 2]);
        }

        if ((g & (NKC - 1)) == (NKC - 1)) {
            // epilogue: score = dot - 0.5*||w||^2, running top-2
            #pragma unroll
            for (int am = 0; am < 2; ++am)
                #pragma unroll
                for (int an = 0; an < 4; ++an)
                    #pragma unroll
                    for (int j = 0; j < 4; ++j) {
                        int h = j >> 1, p = j & 1;
                        float m = acc[am][an][j] - wnv[an][p];
                        int col = tile * BN + wn * 32 + an * 8 + (lane & 3) * 2 + p;
                        if (m > b1[am][h]) {
                            b2[am][h] = b1[am][h]; i2[am][h] = i1[am][h];
                            b1[am][h] = m;         i1[am][h] = col;
                        } else if (m > b2[am][h]) {
                            b2[am][h] = m;         i2[am][h] = col;
                        }
                        acc[am][an][j] = 0.f;
                    }
            ++tile;
            if (tile < NTILE) load_wn(tile);
        }
    }

    CP_WAIT(0);
    __syncthreads();

    // cross-thread reduction to global top-4: 16 slots x 2 candidates per row
    float* rb1 = reinterpret_cast<float*>(smem);
    float* rb2 = rb1 + BM * 16;
    int*   ri1 = reinterpret_cast<int*>(rb2 + BM * 16);
    int*   ri2 = ri1 + BM * 16;
    #pragma unroll
    for (int am = 0; am < 2; ++am)
        #pragma unroll
        for (int h = 0; h < 2; ++h) {
            int rl = wm * 32 + am * 16 + h * 8 + (lane >> 2);
            int slot = wn * 4 + (lane & 3);
            rb1[rl * 16 + slot] = b1[am][h];
            rb2[rl * 16 + slot] = b2[am][h];
            ri1[rl * 16 + slot] = i1[am][h];
            ri2[rl * 16 + slot] = i2[am][h];
        }
    __syncthreads();
    if (tid < BM) {
        float B[4] = {-3.4e38f, -3.4e38f, -3.4e38f, -3.4e38f};
        int   I[4] = {0, 0, 0, 0};
        #pragma unroll
        for (int s = 0; s < 16; ++s) {
            #pragma unroll
            for (int q = 0; q < 2; ++q) {
                float v = q ? rb2[tid * 16 + s] : rb1[tid * 16 + s];
                int   ii = q ? ri2[tid * 16 + s] : ri1[tid * 16 + s];
                #pragma unroll
                for (int r = 0; r < 4; ++r) {
                    if (v > B[r] || (v == B[r] && ii < I[r])) {
                        #pragma unroll
                        for (int q2 = 3; q2 > r; --q2) { B[q2] = B[q2 - 1]; I[q2] = I[q2 - 1]; }
                        B[r] = v; I[r] = ii;
                        break;
                    }
                }
            }
        }
        g_cand[row0 + tid] = make_int4(I[0], I[1], I[2], I[3]);
    }
}

// ============================================================
// fused fixup + gather + loss (fp32 rescore):
// warp per row (8 rows/block); rescore 4 candidates with 4 independent
// fp32 FFMA accumulators + tree reduction; per-block partial loss.
// d(k) = sum_d w*(w - 2x)   (||x||^2 dropped, row-constant)
// ============================================================
__global__ void __launch_bounds__(256)
fixup_gather_kernel(const float* __restrict__ X,
                    const float* __restrict__ W,
                    float* __restrict__ out) {
    const int tid  = threadIdx.x;
    const int wid  = tid >> 5;
    const int lane = tid & 31;
    const int row  = blockIdx.x * 8 + wid;
    const int4 cd = g_cand[row];
    const int cand[4] = {cd.x, cd.y, cd.z, cd.w};
    const float* xr = X + (size_t)row * D_DIM;

    // cache this row's x in registers (reused across 4 candidates)
    float4 xv[4];
    #pragma unroll
    for (int j = 0; j < 4; ++j)
        xv[j] = *reinterpret_cast<const float4*>(xr + lane * 4 + j * 128);

    float bdist = 3.4e38f;
    int   bk = 0x7fffffff;
    #pragma unroll
    for (int c = 0; c < 4; ++c) {
        int k = cand[c];
        const float* wr = W + (size_t)k * D_DIM;
        float s0 = 0.f, s1 = 0.f, s2 = 0.f, s3 = 0.f;
        #pragma unroll
        for (int j = 0; j < 4; ++j) {
            float4 w4 = *reinterpret_cast<const float4*>(wr + lane * 4 + j * 128);
            s0 = fmaf(w4.x, fmaf(-2.f, xv[j].x, w4.x), s0);
            s1 = fmaf(w4.y, fmaf(-2.f, xv[j].y, w4.y), s1);
            s2 = fmaf(w4.z, fmaf(-2.f, xv[j].z, w4.z), s2);
            s3 = fmaf(w4.w, fmaf(-2.f, xv[j].w, w4.w), s3);
        }
        float s = (s0 + s1) + (s2 + s3);
        #pragma unroll
        for (int o = 16; o > 0; o >>= 1)
            s += __shfl_xor_sync(0xffffffffu, s, o);
        // all lanes hold identical s -> identical (bdist, bk)
        if (s < bdist || (s == bdist && k < bk)) { bdist = s; bk = k; }
    }

    // gather + per-warp loss
    const float* wr = W + (size_t)bk * D_DIM;
    float* orow = out + (size_t)row * D_DIM;
    float s = 0.f;
    #pragma unroll
    for (int j = 0; j < 4; ++j) {
        int dd = lane * 4 + j * 128;
        float4 q = *reinterpret_cast<const float4*>(wr + dd);
        *reinterpret_cast<float4*>(orow + dd) = q;
        float dx = q.x - xv[j].x, dy = q.y - xv[j].y, dz = q.z - xv[j].z, dw = q.w - xv[j].w;
        s += dx * dx + dy * dy + dz * dz + dw * dw;
    }
    #pragma unroll
    for (int o = 16; o > 0; o >>= 1) s += __shfl_xor_sync(0xffffffffu, s, o);
    __shared__ float sm[8];
    if (lane == 0) sm[wid] = s;
    __syncthreads();
    if (tid == 0) {
        float t = 0.f;
        #pragma unroll
        for (int i = 0; i < 8; ++i) t += sm[i];
        g_partial[blockIdx.x] = t;   // distinct address per block -> no atomic
    }
}

// ============================================================
// final loss: reduce 2048 partials (1 block, 256 threads)
// ============================================================
__global__ void __launch_bounds__(256)
loss_kernel(float* __restrict__ out, int pos) {
    int tid = threadIdx.x;
    float s = 0.f;
    #pragma unroll
    for (int i = 0; i < NFIX / 256; ++i)
        s += g_partial[i * 256 + tid];
    #pragma unroll
    for (int o = 16; o > 0; o >>= 1) s += __shfl_xor_sync(0xffffffffu, s, o);
    __shared__ float sm[8];
    if ((tid & 31) == 0) sm[tid >> 5] = s;
    __syncthreads();
    if (tid == 0) {
        float t = 0.f;
        #pragma unroll
        for (int i = 0; i < 8; ++i) t += sm[i];
        out[pos] = 1.25f * t / (float)(N_ROWS * D_DIM);
    }
}

// ============================================================
extern "C" void kernel_launch(void* const* d_in, const int* in_sizes, int n_in,
                              void* d_out, int out_size) {
    const float* x = (const float*)d_in[0];
    const float* W = (const float*)d_in[1];
    if (in_sizes[0] == K_CODES * D_DIM && in_sizes[1] == N_ROWS * D_DIM) {
        const float* t = x; x = W; W = t;
    }
    float* out = (float*)d_out;

    cudaFuncSetAttribute(argmin_mma, cudaFuncAttributeMaxDynamicSharedMemorySize, SMEM_DYN);

    split_x_kernel     <<<(N_ROWS * D_DIM / 4) / 256, 256>>>(x);
    split_wnorm_kernel <<<K_CODES, 128>>>(W);
    argmin_mma         <<<N_ROWS / BM, 512, SMEM_DYN>>>();
    fixup_gather_kernel<<<NFIX, 256>>>(x, W, out);
    loss_kernel        <<<1, 256>>>(out, out_size - 1);
}

// round 16
// speedup vs baseline: 2.7870x; 1.0116x over previous
#include <cuda_runtime.h>
#include <cuda_fp16.h>
#include <cstdint>

#define N_ROWS  16384
#define D_DIM   512
#define K_CODES 8192

#define BM 128
#define BN 256           // CTA code-tile width
#define KC 64            // depth per chunk
#define NKC 8            // 512/64
#define NTILE 32         // 8192/256
#define PITCH_B 144      // 128 data bytes + 16 pad (conflict-free ldmatrix)
#define A_PLANE (128 * PITCH_B)              // 18432
#define W_PLANE (256 * PITCH_B)              // 36864
#define A_BYTES (NKC * A_PLANE)              // 147456 (A resident: 8 chunk planes)
#define SMEM_DYN (A_BYTES + 2 * W_PLANE)     // 221184

#define NFIX (N_ROWS / 8)                    // 2048 fixup blocks

// ---------------- device scratch (static: no allocations) ----------------
__device__ __half g_xh[N_ROWS * D_DIM];
__device__ __half g_wh[K_CODES * D_DIM];
__device__ float g_wnorm[K_CODES];
__device__ int4  g_cand[N_ROWS];
__device__ float g_partial[NFIX];

// ---------------- helpers ----------------
__device__ __forceinline__ uint32_t smem_u32(const void* p) {
    uint32_t a;
    asm("{ .reg .u64 t; cvta.to.shared.u64 t, %1; cvt.u32.u64 %0, t; }" : "=r"(a) : "l"(p));
    return a;
}

__device__ __forceinline__ void ldsm4(uint32_t* r, uint32_t addr) {
    asm volatile("ldmatrix.sync.aligned.m8n8.x4.shared.b16 {%0,%1,%2,%3}, [%4];"
                 : "=r"(r[0]), "=r"(r[1]), "=r"(r[2]), "=r"(r[3]) : "r"(addr));
}

__device__ __forceinline__ void mma16816(float* c, const uint32_t* a,
                                         uint32_t b0, uint32_t b1) {
    asm volatile(
        "mma.sync.aligned.m16n8k16.row.col.f32.f16.f16.f32 "
        "{%0,%1,%2,%3}, {%4,%5,%6,%7}, {%8,%9}, {%0,%1,%2,%3};"
        : "+f"(c[0]), "+f"(c[1]), "+f"(c[2]), "+f"(c[3])
        : "r"(a[0]), "r"(a[1]), "r"(a[2]), "r"(a[3]), "r"(b0), "r"(b1));
}

#define CP_ASYNC16(dst, src) \
    asm volatile("cp.async.cg.shared.global [%0], [%1], 16;" :: "r"(dst), "l"(src))
#define CP_COMMIT()   asm volatile("cp.async.commit_group;" ::: "memory")
#define CP_WAIT(n)    asm volatile("cp.async.wait_group %0;" :: "n"(n) : "memory")

// ============================================================
// convert X -> fp16
// ============================================================
__global__ void split_x_kernel(const float* __restrict__ src) {
    int i = blockIdx.x * blockDim.x + threadIdx.x;   // over float4s
    float4 v = reinterpret_cast<const float4*>(src)[i];
    reinterpret_cast<__half2*>(g_xh)[i * 2]     = __floats2half2_rn(v.x, v.y);
    reinterpret_cast<__half2*>(g_xh)[i * 2 + 1] = __floats2half2_rn(v.z, v.w);
}

// ============================================================
// convert W -> fp16 + ||w||^2  (one pass over W)
// ============================================================
__global__ void split_wnorm_kernel(const float* __restrict__ W) {
    int k = blockIdx.x;
    const float* row = W + (size_t)k * D_DIM;
    int d = threadIdx.x * 4;
    float4 v = *reinterpret_cast<const float4*>(row + d);
    __half2* dst = reinterpret_cast<__half2*>(g_wh + (size_t)k * D_DIM + d);
    dst[0] = __floats2half2_rn(v.x, v.y);
    dst[1] = __floats2half2_rn(v.z, v.w);
    float s = v.x * v.x + v.y * v.y + v.z * v.z + v.w * v.w;
    #pragma unroll
    for (int o = 16; o > 0; o >>= 1) s += __shfl_xor_sync(0xffffffffu, s, o);
    __shared__ float sm[4];
    if ((threadIdx.x & 31) == 0) sm[threadIdx.x >> 5] = s;
    __syncthreads();
    if (threadIdx.x == 0) g_wnorm[k] = sm[0] + sm[1] + sm[2] + sm[3];
}

// ============================================================
// fused fp16 HMMA GEMM + top-4 argmax candidates
// CTA tile 128x256; warp tile 32x64 (16 warps, wm4 x wn4)
// A (X tile) RESIDENT in smem (8 KC-planes); W streamed, 2 stages
// ============================================================
__global__ void __launch_bounds__(512, 1)
argmin_mma() {
    extern __shared__ __align__(16) char smem[];
    const uint32_t sb = smem_u32(smem);
    const int tid  = threadIdx.x;
    const int lane = tid & 31;
    const int wid  = tid >> 5;
    const int wm = wid >> 2;          // 0..3 : 32-row slab
    const int wn = wid & 3;           // 0..3 : 64-col slab
    const int row0 = blockIdx.x * BM;

    const uint32_t lm_off = (uint32_t)((lane & 15) * PITCH_B + (lane >> 4) * 16);
    const uint32_t a_base_row = (uint32_t)(wm * 32) * PITCH_B;
    const uint32_t b_base_row = (uint32_t)(wn * 64) * PITCH_B;

    float acc[2][8][4];
    #pragma unroll
    for (int am = 0; am < 2; ++am)
        #pragma unroll
        for (int an = 0; an < 8; ++an)
            #pragma unroll
            for (int j = 0; j < 4; ++j) acc[am][an][j] = 0.f;

    // per-thread top-2 per (am, h) row
    float b1[2][2], b2[2][2];
    int   i1[2][2], i2[2][2];
    #pragma unroll
    for (int am = 0; am < 2; ++am)
        #pragma unroll
        for (int h = 0; h < 2; ++h) {
            b1[am][h] = b2[am][h] = -3.4e38f;
            i1[am][h] = i2[am][h] = 0;
        }

    // A resident: 8 KC-planes of 128 rows x 128B. 8192 cp16 / 512 thr = 16.
    auto load_A = [&]() {
        #pragma unroll
        for (int it = 0; it < 16; ++it) {
            int v = it * 512 + tid;
            int cg = v >> 10;          // plane 0..7
            int rem = v & 1023;
            int r = rem >> 3, j = rem & 7;
            const __half* s0 = g_xh + (size_t)(row0 + r) * D_DIM + cg * KC + j * 8;
            uint32_t dst = sb + (uint32_t)(cg * A_PLANE + r * PITCH_B + j * 16);
            CP_ASYNC16(dst, s0);
        }
    };

    // W chunk g: tile tg = g>>3, depth chunk cg = g&7 -> stage g&1.
    // 256 rows x 8 segs = 2048 cp16 / 512 thr = 4.
    auto load_W = [&](int g) {
        const int st = g & 1, cg = g & (NKC - 1), tg = g >> 3;
        const uint32_t dbase = sb + A_BYTES + (uint32_t)st * W_PLANE;
        #pragma unroll
        for (int it = 0; it < 4; ++it) {
            int v = it * 512 + tid;
            int r = v >> 3, j = v & 7;
            const __half* s0 = g_wh + (size_t)(tg * BN + r) * D_DIM + cg * KC + j * 8;
            uint32_t dst = dbase + (uint32_t)(r * PITCH_B + j * 16);
            CP_ASYNC16(dst, s0);
        }
    };

    float wnv[8][2];
    auto load_wn = [&](int t) {
        #pragma unroll
        for (int an = 0; an < 8; ++an)
            #pragma unroll
            for (int p = 0; p < 2; ++p)
                wnv[an][p] = 0.5f * __ldg(&g_wnorm[t * BN + wn * 64 + an * 8 + (lane & 3) * 2 + p]);
    };

    // prologue: A resident + W chunk 0
    load_A(); CP_COMMIT();
    load_W(0); CP_COMMIT();
    load_wn(0);

    int tile = 0;
    const int TOTAL = NTILE * NKC;   // 256
    for (int g = 0; g < TOTAL; ++g) {
        CP_WAIT(0);              // chunk g (and A) landed
        __syncthreads();         // all warps done with the stage being overwritten
        if (g + 1 < TOTAL) load_W(g + 1);
        CP_COMMIT();

        const uint32_t abase = sb + (uint32_t)(g & (NKC - 1)) * A_PLANE;
        const uint32_t wbase = sb + A_BYTES + (uint32_t)(g & 1) * W_PLANE;
        #pragma unroll
        for (int ks = 0; ks < 4; ++ks) {
            uint32_t ah[2][4], bh[4][4];
            #pragma unroll
            for (int am = 0; am < 2; ++am) {
                uint32_t ad = abase + a_base_row + (uint32_t)(am * 16 * PITCH_B) + lm_off + ks * 32;
                ldsm4(ah[am], ad);
            }
            #pragma unroll
            for (int bp = 0; bp < 4; ++bp) {
                uint32_t bd = wbase + b_base_row + (uint32_t)(bp * 16 * PITCH_B) + lm_off + ks * 32;
                ldsm4(bh[bp], bd);
            }
            #pragma unroll
            for (int am = 0; am < 2; ++am)
                #pragma unroll
                for (int an = 0; an < 8; ++an)
                    mma16816(acc[am][an], ah[am], bh[an >> 1][an & 1], bh[an >> 1][(an & 1) + 2]);
        }

        if ((g & (NKC - 1)) == (NKC - 1)) {
            // epilogue: score = dot - 0.5*||w||^2, running top-2
            #pragma unroll
            for (int am = 0; am < 2; ++am)
                #pragma unroll
                for (int an = 0; an < 8; ++an)
                    #pragma unroll
                    for (int j = 0; j < 4; ++j) {
                        int h = j >> 1, p = j & 1;
                        float m = acc[am][an][j] - wnv[an][p];
                        int col = tile * BN + wn * 64 + an * 8 + (lane & 3) * 2 + p;
                        if (m > b1[am][h]) {
                            b2[am][h] = b1[am][h]; i2[am][h] = i1[am][h];
                            b1[am][h] = m;         i1[am][h] = col;
                        } else if (m > b2[am][h]) {
                            b2[am][h] = m;         i2[am][h] = col;
                        }
                        acc[am][an][j] = 0.f;
                    }
            ++tile;
            if (tile < NTILE) load_wn(tile);
        }
    }

    CP_WAIT(0);
    __syncthreads();

    // cross-thread reduction to global top-4: 16 slots x 2 candidates per row
    float* rb1 = reinterpret_cast<float*>(smem);
    float* rb2 = rb1 + BM * 16;
    int*   ri1 = reinterpret_cast<int*>(rb2 + BM * 16);
    int*   ri2 = ri1 + BM * 16;
    #pragma unroll
    for (int am = 0; am < 2; ++am)
        #pragma unroll
        for (int h = 0; h < 2; ++h) {
            int rl = wm * 32 + am * 16 + h * 8 + (lane >> 2);
            int slot = wn * 4 + (lane & 3);
            rb1[rl * 16 + slot] = b1[am][h];
            rb2[rl * 16 + slot] = b2[am][h];
            ri1[rl * 16 + slot] = i1[am][h];
            ri2[rl * 16 + slot] = i2[am][h];
        }
    __syncthreads();
    if (tid < BM) {
        float B[4] = {-3.4e38f, -3.4e38f, -3.4e38f, -3.4e38f};
        int   I[4] = {0, 0, 0, 0};
        #pragma unroll
        for (int s = 0; s < 16; ++s) {
            #pragma unroll
            for (int q = 0; q < 2; ++q) {
                float v = q ? rb2[tid * 16 + s] : rb1[tid * 16 + s];
                int   ii = q ? ri2[tid * 16 + s] : ri1[tid * 16 + s];
                #pragma unroll
                for (int r = 0; r < 4; ++r) {
                    if (v > B[r] || (v == B[r] && ii < I[r])) {
                        #pragma unroll
                        for (int q2 = 3; q2 > r; --q2) { B[q2] = B[q2 - 1]; I[q2] = I[q2 - 1]; }
                        B[r] = v; I[r] = ii;
                        break;
                    }
                }
            }
        }
        g_cand[row0 + tid] = make_int4(I[0], I[1], I[2], I[3]);
    }
}

// ============================================================
// fused fixup + gather + loss (fp32 rescore):
// warp per row (8 rows/block); rescore 4 candidates with 4 independent
// fp32 FFMA accumulators + tree reduction; per-block partial loss.
// d(k) = sum_d w*(w - 2x)   (||x||^2 dropped, row-constant)
// ============================================================
__global__ void __launch_bounds__(256)
fixup_gather_kernel(const float* __restrict__ X,
                    const float* __restrict__ W,
                    float* __restrict__ out) {
    const int tid  = threadIdx.x;
    const int wid  = tid >> 5;
    const int lane = tid & 31;
    const int row  = blockIdx.x * 8 + wid;
    const int4 cd = g_cand[row];
    const int cand[4] = {cd.x, cd.y, cd.z, cd.w};
    const float* xr = X + (size_t)row * D_DIM;

    // cache this row's x in registers (reused across 4 candidates)
    float4 xv[4];
    #pragma unroll
    for (int j = 0; j < 4; ++j)
        xv[j] = *reinterpret_cast<const float4*>(xr + lane * 4 + j * 128);

    float bdist = 3.4e38f;
    int   bk = 0x7fffffff;
    #pragma unroll
    for (int c = 0; c < 4; ++c) {
        int k = cand[c];
        const float* wr = W + (size_t)k * D_DIM;
        float s0 = 0.f, s1 = 0.f, s2 = 0.f, s3 = 0.f;
        #pragma unroll
        for (int j = 0; j < 4; ++j) {
            float4 w4 = *reinterpret_cast<const float4*>(wr + lane * 4 + j * 128);
            s0 = fmaf(w4.x, fmaf(-2.f, xv[j].x, w4.x), s0);
            s1 = fmaf(w4.y, fmaf(-2.f, xv[j].y, w4.y), s1);
            s2 = fmaf(w4.z, fmaf(-2.f, xv[j].z, w4.z), s2);
            s3 = fmaf(w4.w, fmaf(-2.f, xv[j].w, w4.w), s3);
        }
        float s = (s0 + s1) + (s2 + s3);
        #pragma unroll
        for (int o = 16; o > 0; o >>= 1)
            s += __shfl_xor_sync(0xffffffffu, s, o);
        // all lanes hold identical s -> identical (bdist, bk)
        if (s < bdist || (s == bdist && k < bk)) { bdist = s; bk = k; }
    }

    // gather + per-warp loss
    const float* wr = W + (size_t)bk * D_DIM;
    float* orow = out + (size_t)row * D_DIM;
    float s = 0.f;
    #pragma unroll
    for (int j = 0; j < 4; ++j) {
        int dd = lane * 4 + j * 128;
        float4 q = *reinterpret_cast<const float4*>(wr + dd);
        *reinterpret_cast<float4*>(orow + dd) = q;
        float dx = q.x - xv[j].x, dy = q.y - xv[j].y, dz = q.z - xv[j].z, dw = q.w - xv[j].w;
        s += dx * dx + dy * dy + dz * dz + dw * dw;
    }
    #pragma unroll
    for (int o = 16; o > 0; o >>= 1) s += __shfl_xor_sync(0xffffffffu, s, o);
    __shared__ float sm[8];
    if (lane == 0) sm[wid] = s;
    __syncthreads();
    if (tid == 0) {
        float t = 0.f;
        #pragma unroll
        for (int i = 0; i < 8; ++i) t += sm[i];
        g_partial[blockIdx.x] = t;   // distinct address per block -> no atomic
    }
}

// ============================================================
// final loss: reduce 2048 partials (1 block, 256 threads)
// ============================================================
__global__ void __launch_bounds__(256)
loss_kernel(float* __restrict__ out, int pos) {
    int tid = threadIdx.x;
    float s = 0.f;
    #pragma unroll
    for (int i = 0; i < NFIX / 256; ++i)
        s += g_partial[i * 256 + tid];
    #pragma unroll
    for (int o = 16; o > 0; o >>= 1) s += __shfl_xor_sync(0xffffffffu, s, o);
    __shared__ float sm[8];
    if ((tid & 31) == 0) sm[tid >> 5] = s;
    __syncthreads();
    if (tid == 0) {
        float t = 0.f;
        #pragma unroll
        for (int i = 0; i < 8; ++i) t += sm[i];
        out[pos] = 1.25f * t / (float)(N_ROWS * D_DIM);
    }
}

// ============================================================
extern "C" void kernel_launch(void* const* d_in, const int* in_sizes, int n_in,
                              void* d_out, int out_size) {
    const float* x = (const float*)d_in[0];
    const float* W = (const float*)d_in[1];
    if (in_sizes[0] == K_CODES * D_DIM && in_sizes[1] == N_ROWS * D_DIM) {
        const float* t = x; x = W; W = t;
    }
    float* out = (float*)d_out;

    cudaFuncSetAttribute(argmin_mma, cudaFuncAttributeMaxDynamicSharedMemorySize, SMEM_DYN);

    split_x_kernel     <<<(N_ROWS * D_DIM / 4) / 256, 256>>>(x);
    split_wnorm_kernel <<<K_CODES, 128>>>(W);
    argmin_mma         <<<N_ROWS / BM, 512, SMEM_DYN>>>();
    fixup_gather_kernel<<<NFIX, 256>>>(x, W, out);
    loss_kernel        <<<1, 256>>>(out, out_size - 1);
}